// round 14
// baseline (speedup 1.0000x reference)
#include <cuda_runtime.h>
#include <cuda_fp16.h>
#include <cstdint>

#define DTC   0.001f
#define HID   512
#define NOUT  128
#define SEQL  2048
#define NB    64
#define MROWS (SEQL * NB)     // 131072 output rows, m = s*64 + b
#define NCH   (NB * NOUT)     // 8192 recurrence chains
#define SEG_P 32
#define SEG_L 64

// ---------------- scratch (no allocation allowed) ----------------
__device__ __align__(16) float g_segE_v[SEG_P * NCH];
__device__ __align__(16) float g_segE_i[SEG_P * NCH];
__device__ __align__(16) float g_init_v[SEG_P * NCH];
__device__ __align__(16) float g_init_i[SEG_P * NCH];
__device__ __align__(16) __half g_Wh[NOUT * HID];

// ---------------- helpers ----------------
__device__ __forceinline__ uint32_t smem_u32(const void* p) {
    uint32_t a;
    asm("{ .reg .u64 t; cvta.to.shared.u64 t, %1; cvt.u32.u64 %0, t; }" : "=r"(a) : "l"(p));
    return a;
}
__device__ __forceinline__ void ldsm_x4(uint32_t* r, uint32_t addr) {
    asm volatile("ldmatrix.sync.aligned.m8n8.x4.shared.b16 {%0,%1,%2,%3}, [%4];"
                 : "=r"(r[0]), "=r"(r[1]), "=r"(r[2]), "=r"(r[3]) : "r"(addr));
}
__device__ __forceinline__ void mma_f16(float* c, const uint32_t* a,
                                        uint32_t b0, uint32_t b1) {
    asm volatile(
        "mma.sync.aligned.m16n8k16.row.col.f32.f16.f16.f32 "
        "{%0,%1,%2,%3}, {%4,%5,%6,%7}, {%8,%9}, {%0,%1,%2,%3};"
        : "+f"(c[0]), "+f"(c[1]), "+f"(c[2]), "+f"(c[3])
        : "r"(a[0]), "r"(a[1]), "r"(a[2]), "r"(a[3]), "r"(b0), "r"(b1));
}
__device__ __forceinline__ void cp16(uint32_t smaddr, const void* g) {
    asm volatile("cp.async.cg.shared.global [%0], [%1], 16;"
                 :: "r"(smaddr), "l"(g) : "memory");
}
#define CP_COMMIT() asm volatile("cp.async.commit_group;" ::: "memory")
#define CP_WAIT0()  asm volatile("cp.async.wait_group 0;" ::: "memory")

__device__ __forceinline__ uint32_t h2u(__half2 v) {
    return *reinterpret_cast<uint32_t*>(&v);
}
__device__ __forceinline__ uint2 cvt4h(float4 f) {
    uint2 r;
    r.x = h2u(__floats2half2_rn(f.x, f.y));
    r.y = h2u(__floats2half2_rn(f.z, f.w));
    return r;
}

// ---------------------------------------------------------------------------
__global__ __launch_bounds__(256)
void w_preconv(const float* __restrict__ W) {
    const int i = blockIdx.x * 256 + threadIdx.x;
    g_Wh[i] = __float2half_rn(W[i]);
}

// ---------------------------------------------------------------------------
// GEMM: z = fp16(x) * fp16(W), single product, fp32 accumulate.
// CTA tile 64x128, BK=32 (16 chunks), double-buffered, 256 threads / 8 warps,
// warp tile 32x32, 3 CTAs per SM (24 warps). Rows 64B padded to 80B.
// FIX vs R13: B copy now covers the full 32 bytes per thread (two cp16).
// ---------------------------------------------------------------------------
#define ROWB   80
#define AMATB  (64 * ROWB)           // 5120 bytes (A tile, 64 rows)
#define BMATB  (128 * ROWB)          // 10240 bytes (B tile, 128 cols)
#define BUFB   (AMATB + BMATB)       // 15360
#define SMEMB  (2 * BUFB)            // 30720 -> 3 CTAs/SM

extern __shared__ char dynsmem[];

__global__ __launch_bounds__(256, 3)
void snn_gemm_f16(const float* __restrict__ x, float* __restrict__ z) {
    const int tid  = threadIdx.x;
    const int wid  = tid >> 5;
    const int lane = tid & 31;
    const int m0   = blockIdx.x * 64;
    const int wm   = wid & 1;        // 2 M groups of 32
    const int wn   = wid >> 1;       // 4 N groups of 32

    const uint32_t sm = smem_u32(dynsmem);

    // ---- A mapping: 64 rows x 32 floats per chunk; 4 threads/row, 8 floats ----
    const int rA = tid >> 2;             // 0..63
    const int hA = (tid & 3) * 8;        // float offset
    const int mA = m0 + rA;
    const float* pA = x + ((size_t)(mA & 63) * SEQL + (size_t)(mA >> 6)) * HID + hA;
    const uint32_t st0 = (uint32_t)rA * ROWB + (uint32_t)hA * 2;

    // ---- B cp.async: 128 rows x 64B per chunk; 2 threads/row, 32B each ----
    const int rB = tid >> 1;             // 0..127
    const int hB = (tid & 1) * 16;       // halves
    const __half* pB = g_Wh + (size_t)rB * HID + hB;
    const uint32_t bDst = (uint32_t)AMATB + (uint32_t)rB * ROWB + (uint32_t)hB * 2;

    // ---- ldsm source addresses ----
    uint32_t aAddr[2];
#pragma unroll
    for (int i = 0; i < 2; i++) {
        const int arow = wm * 32 + i * 16 + (lane & 15);
        aAddr[i] = sm + (uint32_t)arow * ROWB + ((lane >> 4) & 1) * 16;
    }
    uint32_t bAddr[2];
#pragma unroll
    for (int g = 0; g < 2; g++) {
        const int bcol = wn * 32 + g * 16 + ((lane >> 4) & 1) * 8 + (lane & 7);
        bAddr[g] = sm + (uint32_t)AMATB + (uint32_t)bcol * ROWB +
                   ((lane >> 3) & 1) * 16;
    }

    float acc[2][4][4];
#pragma unroll
    for (int i = 0; i < 2; i++)
#pragma unroll
        for (int j = 0; j < 4; j++)
#pragma unroll
            for (int q = 0; q < 4; q++) acc[i][j][q] = 0.f;

    float4 rgA[2];
    auto loadA = [&](int c) {
        rgA[0] = *(const float4*)(pA + c * 32);
        rgA[1] = *(const float4*)(pA + c * 32 + 4);
    };
    auto storeA = [&](char* base) {
        *(uint2*)(base + st0)     = cvt4h(rgA[0]);
        *(uint2*)(base + st0 + 8) = cvt4h(rgA[1]);
    };
    auto cpB = [&](uint32_t bufb, int c) {
        cp16(sm + bufb + bDst,      pB + c * 32);
        cp16(sm + bufb + bDst + 16, pB + c * 32 + 8);
    };

    // ---- prologue ----
    loadA(0);
    storeA(dynsmem);
    cpB(0, 0);
    CP_COMMIT();
    loadA(1);

    for (int c = 0; c < 16; c++) {
        const int cb = c & 1;
        CP_WAIT0();
        __syncthreads();
        if (c < 15) {
            storeA(dynsmem + (cb ^ 1) * BUFB);
            cpB((uint32_t)(cb ^ 1) * BUFB, c + 1);
            CP_COMMIT();
            if (c < 14) loadA(c + 2);
        }
        // ---- compute on buf cb: two k16 steps ----
        const uint32_t bb = (uint32_t)cb * BUFB;
#pragma unroll
        for (int ks = 0; ks < 2; ks++) {
            const uint32_t ko = (uint32_t)ks * 32;
            uint32_t a[2][4];
#pragma unroll
            for (int i = 0; i < 2; i++)
                ldsm_x4(a[i], aAddr[i] + bb + ko);
            uint32_t b[8];
            ldsm_x4(b + 0, bAddr[0] + bb + ko);
            ldsm_x4(b + 4, bAddr[1] + bb + ko);
#pragma unroll
            for (int i = 0; i < 2; i++)
#pragma unroll
                for (int j = 0; j < 4; j++)
                    mma_f16(acc[i][j], a[i], b[2 * j], b[2 * j + 1]);
        }
    }

    // ---- epilogue ----
    const int r0 = lane >> 2;
    const int c0 = (lane & 3) * 2;
#pragma unroll
    for (int i = 0; i < 2; i++) {
        const int mrow = m0 + wm * 32 + i * 16 + r0;
#pragma unroll
        for (int j = 0; j < 4; j++) {
            const int col = wn * 32 + j * 8 + c0;
            *(float2*)&z[(size_t)mrow * NOUT + col] =
                make_float2(acc[i][j][0], acc[i][j][1]);
            *(float2*)&z[(size_t)(mrow + 8) * NOUT + col] =
                make_float2(acc[i][j][2], acc[i][j][3]);
        }
    }
}

// ---------------------------------------------------------------------------
// Scan stage A: zero-state segment responses, 4 chains/thread, 16-deep buffer.
// ---------------------------------------------------------------------------
__global__ __launch_bounds__(256)
void scan_segA(const float* __restrict__ zv,
               const float* __restrict__ tau_syn, const float* __restrict__ tau_mem) {
    const int t = blockIdx.x * 256 + threadIdx.x;
    const int ch4 = (t & 2047) * 4;
    const int p = t >> 11;
    const float tm = fminf(fmaxf(tau_mem[0], 0.f), 1.f);
    const float ts = fminf(fmaxf(tau_syn[0], 0.f), 1.f);
    const float A = DTC * tm, B = DTC * ts;

    const float* zp = zv + (size_t)(p * SEG_L) * NCH + ch4;
    float v[4] = {0, 0, 0, 0}, cu[4] = {0, 0, 0, 0};
    float4 buf[16];
#pragma unroll
    for (int g = 0; g < SEG_L; g += 16) {
#pragma unroll
        for (int j = 0; j < 16; j++) buf[j] = *(const float4*)(zp + (g + j) * NCH);
#pragma unroll
        for (int j = 0; j < 16; j++) {
            const float* zb = (const float*)&buf[j];
#pragma unroll
            for (int q = 0; q < 4; q++) {
                v[q]  = fmaf(A, cu[q] - v[q], v[q]);
                cu[q] = fmaf(-B, cu[q], cu[q]) + zb[q];
            }
        }
    }
    *(float4*)&g_segE_v[p * NCH + ch4] = make_float4(v[0], v[1], v[2], v[3]);
    *(float4*)&g_segE_i[p * NCH + ch4] = make_float4(cu[0], cu[1], cu[2], cu[3]);
}

// ---------------------------------------------------------------------------
// Scan stage B: per chain, scan SEG_P summaries (all loads prefetched).
// ---------------------------------------------------------------------------
__global__ __launch_bounds__(256)
void scan_segB(const float* __restrict__ tau_syn, const float* __restrict__ tau_mem) {
    const int chain = blockIdx.x * 256 + threadIdx.x;
    const float tm = fminf(fmaxf(tau_mem[0], 0.f), 1.f);
    const float ts = fminf(fmaxf(tau_syn[0], 0.f), 1.f);
    const float A = DTC * tm, B = DTC * ts;
    const float a = 1.f - A, b = 1.f - B;

    float ev[SEG_P], ei[SEG_P];
#pragma unroll
    for (int p = 0; p < SEG_P; p++) {
        ev[p] = g_segE_v[p * NCH + chain];
        ei[p] = g_segE_i[p * NCH + chain];
    }

    float pa = 1.f, pc = 0.f, pb = 1.f;   // M^SEG_L = [[pa,pc],[0,pb]]
#pragma unroll
    for (int k = 0; k < SEG_L; k++) {
        pc = a * pc + A * pb;
        pa = a * pa;
        pb = b * pb;
    }

    float v = 0.f, cur = 0.f;
#pragma unroll
    for (int p = 0; p < SEG_P; p++) {
        g_init_v[p * NCH + chain] = v;
        g_init_i[p * NCH + chain] = cur;
        const float nv = pa * v + pc * cur + ev[p];
        const float ni = pb * cur + ei[p];
        v = nv; cur = ni;
    }
}

// ---------------------------------------------------------------------------
// Scan stage C: exact per-segment recompute + in-place voltage write, x4.
// ---------------------------------------------------------------------------
__global__ __launch_bounds__(256)
void scan_segC(float* __restrict__ zv, float* __restrict__ vf, float* __restrict__ iff,
               const float* __restrict__ tau_syn, const float* __restrict__ tau_mem,
               int write_finals) {
    const int t = blockIdx.x * 256 + threadIdx.x;
    const int ch4 = (t & 2047) * 4;
    const int p = t >> 11;
    const float tm = fminf(fmaxf(tau_mem[0], 0.f), 1.f);
    const float ts = fminf(fmaxf(tau_syn[0], 0.f), 1.f);
    const float A = DTC * tm, B = DTC * ts;

    float4 v4 = *(const float4*)&g_init_v[p * NCH + ch4];
    float4 i4 = *(const float4*)&g_init_i[p * NCH + ch4];
    float v[4] = {v4.x, v4.y, v4.z, v4.w};
    float cu[4] = {i4.x, i4.y, i4.z, i4.w};

    float* zp = zv + (size_t)(p * SEG_L) * NCH + ch4;
    float4 buf[16];
#pragma unroll
    for (int g = 0; g < SEG_L; g += 16) {
#pragma unroll
        for (int j = 0; j < 16; j++) buf[j] = *(const float4*)(zp + (g + j) * NCH);
#pragma unroll
        for (int j = 0; j < 16; j++) {
            const float* zb = (const float*)&buf[j];
            float4 vo;
#pragma unroll
            for (int q = 0; q < 4; q++) {
                v[q] = fmaf(A, cu[q] - v[q], v[q]);
                ((float*)&vo)[q] = v[q];
                cu[q] = fmaf(-B, cu[q], cu[q]) + zb[q];
            }
            *(float4*)(zp + (g + j) * NCH) = vo;
        }
    }
    if (write_finals && p == SEG_P - 1) {
        *(float4*)&vf[ch4]  = make_float4(v[0], v[1], v[2], v[3]);
        *(float4*)&iff[ch4] = make_float4(cu[0], cu[1], cu[2], cu[3]);
    }
}

// ---------------------------------------------------------------------------
extern "C" void kernel_launch(void* const* d_in, const int* in_sizes, int n_in,
                              void* d_out, int out_size) {
    const float* x = nullptr;
    const float* W = nullptr;
    const float* t_syn = nullptr;
    const float* t_mem = nullptr;
    for (int i = 0; i < n_in; i++) {
        if (in_sizes[i] == MROWS * HID)     x = (const float*)d_in[i];
        else if (in_sizes[i] == NOUT * HID) W = (const float*)d_in[i];
        else if (in_sizes[i] == 1) {
            if (!t_syn) t_syn = (const float*)d_in[i];
            else        t_mem = (const float*)d_in[i];
        }
    }

    float* out = (float*)d_out;
    const int vol = SEQL * NCH;
    const int write_finals = (out_size >= vol + 2 * NCH) ? 1 : 0;

    static int smem_set = 0;
    if (!smem_set) {
        cudaFuncSetAttribute(snn_gemm_f16,
                             cudaFuncAttributeMaxDynamicSharedMemorySize, SMEMB);
        smem_set = 1;
    }

    w_preconv<<<(NOUT * HID) / 256, 256>>>(W);
    snn_gemm_f16<<<MROWS / 64, 256, SMEMB>>>(x, out);
    scan_segA<<<(SEG_P * NCH / 4) / 256, 256>>>(out, t_syn, t_mem);
    scan_segB<<<NCH / 256, 256>>>(t_syn, t_mem);
    scan_segC<<<(SEG_P * NCH / 4) / 256, 256>>>(out, out + vol, out + vol + NCH,
                                                t_syn, t_mem, write_finals);
}